// round 3
// baseline (speedup 1.0000x reference)
#include <cuda_runtime.h>
#include <math.h>

#define BB 16
#define CC 128
#define HW 4096
#define NHEAD 8
#define HDIM 16
#define BH 128
#define OC3 384
#define OUTC 512

// Scratch (allocation-free rule: __device__ globals)
__device__ float g_s[(size_t)BB * CC * HW];        // CPE output
__device__ float g_qkv[(size_t)BB * OC3 * HW];     // qkv per batch [384][4096]
__device__ float g_poslam[(size_t)BB * CC * HW];   // position lambda
__device__ float g_res1[(size_t)BB * CC * HW];     // result1
__device__ float g_pool[BB * CC];
__device__ float g_ca[BB * CC];
__device__ float g_kmax[BH * HDIM];
__device__ float g_ksum[BH * HDIM];
__device__ float g_lam[BH * HDIM * HDIM];

// ---------------- CPE: depthwise 3x3 + residual ----------------
__global__ void k_cpe(const float* __restrict__ src, const float* __restrict__ cpe_w) {
    int bc = blockIdx.x;              // b*C + c
    int c = bc & (CC - 1);
    const float* plane = src + (size_t)bc * HW;
    __shared__ float t[66][66];
    for (int i = threadIdx.x; i < 66 * 66; i += blockDim.x) {
        int r = i / 66, q = i % 66;
        int rr = r - 1, qq = q - 1;
        t[r][q] = (rr >= 0 && rr < 64 && qq >= 0 && qq < 64) ? plane[rr * 64 + qq] : 0.f;
    }
    __syncthreads();
    float w[9];
#pragma unroll
    for (int j = 0; j < 9; j++) w[j] = cpe_w[c * 9 + j];
    for (int p = threadIdx.x; p < HW; p += blockDim.x) {
        int r = p >> 6, q = p & 63;
        float acc = t[r + 1][q + 1];  // residual
#pragma unroll
        for (int dr = 0; dr < 3; dr++)
#pragma unroll
            for (int dc = 0; dc < 3; dc++)
                acc += w[dr * 3 + dc] * t[r + dr][q + dc];
        g_s[(size_t)bc * HW + p] = acc;
    }
}

// ---------------- pooled mean per (b,c) ----------------
__global__ void k_pool(const float* __restrict__ src) {
    int bc = blockIdx.x;
    const float* plane = src + (size_t)bc * HW;
    float s = 0.f;
    for (int p = threadIdx.x; p < HW; p += 256) s += plane[p];
    __shared__ float red[8];
#pragma unroll
    for (int off = 16; off; off >>= 1) s += __shfl_down_sync(0xffffffffu, s, off);
    if ((threadIdx.x & 31) == 0) red[threadIdx.x >> 5] = s;
    __syncthreads();
    if (threadIdx.x < 8) {
        s = red[threadIdx.x];
#pragma unroll
        for (int off = 4; off; off >>= 1) s += __shfl_down_sync(0xffu, s, off);
        if (threadIdx.x == 0) g_pool[bc] = s * (1.f / HW);
    }
}

// ---------------- ECA conv1d + sigmoid ----------------
__global__ void k_ca(const float* __restrict__ w3) {
    int b = blockIdx.x, c = threadIdx.x;
    const float* pp = g_pool + b * CC;
    float x0 = (c > 0) ? pp[c - 1] : 0.f;
    float x1 = pp[c];
    float x2 = (c < CC - 1) ? pp[c + 1] : 0.f;
    float z = w3[0] * x0 + w3[1] * x1 + w3[2] * x2;
    g_ca[b * CC + c] = 1.f / (1.f + expf(-z));
}

// ---------------- QKV GEMM: qkv[b][o][n] = sum_k W[o][k] * s[b][k][n] ----------------
__global__ void k_gemm_qkv(const float* __restrict__ Wm) {
    const int BM = 64, BN = 64, BK = 32, KC = 128;
    __shared__ float Ws[BK][BM + 1];
    __shared__ float Is[BK][BN + 4];
    int b = blockIdx.z;
    int o0 = blockIdx.y * BM;
    int n0 = blockIdx.x * BN;
    const float* Inb = g_s + (size_t)b * KC * HW;
    int tid = threadIdx.x, tx = tid & 15, ty = tid >> 4;
    float acc[4][4] = {};
    for (int k0 = 0; k0 < KC; k0 += BK) {
        for (int i = tid; i < BM * BK; i += 256) {
            int o = i >> 5, k = i & 31;
            Ws[k][o] = Wm[(o0 + o) * KC + k0 + k];
        }
        for (int i = tid; i < BK * BN; i += 256) {
            int k = i >> 6, n = i & 63;
            Is[k][n] = Inb[(size_t)(k0 + k) * HW + n0 + n];
        }
        __syncthreads();
#pragma unroll
        for (int kk = 0; kk < BK; kk++) {
            float a[4], bv[4];
#pragma unroll
            for (int i = 0; i < 4; i++) a[i] = Ws[kk][ty * 4 + i];
#pragma unroll
            for (int j = 0; j < 4; j++) bv[j] = Is[kk][tx * 4 + j];
#pragma unroll
            for (int i = 0; i < 4; i++)
#pragma unroll
                for (int j = 0; j < 4; j++)
                    acc[i][j] += a[i] * bv[j];
        }
        __syncthreads();
    }
    float* Ob = g_qkv + (size_t)b * OC3 * HW;
#pragma unroll
    for (int i = 0; i < 4; i++)
#pragma unroll
        for (int j = 0; j < 4; j++)
            Ob[(size_t)(o0 + ty * 4 + i) * HW + n0 + tx * 4 + j] = acc[i][j];
}

// ---------------- softmax stats over spatial dim of k ----------------
__global__ void k_kstats() {
    int row = blockIdx.x;            // bh*16 + i
    int bh = row >> 4, i = row & 15;
    int b = bh >> 3, nh = bh & 7;
    const float* kp = g_qkv + ((size_t)b * OC3 + CC + nh * HDIM + i) * HW;
    __shared__ float red[8];
    __shared__ float bcast;

    float m = -1e30f;
    for (int p = threadIdx.x; p < HW; p += 256) m = fmaxf(m, kp[p]);
#pragma unroll
    for (int off = 16; off; off >>= 1) m = fmaxf(m, __shfl_down_sync(0xffffffffu, m, off));
    if ((threadIdx.x & 31) == 0) red[threadIdx.x >> 5] = m;
    __syncthreads();
    if (threadIdx.x < 8) {
        m = red[threadIdx.x];
#pragma unroll
        for (int off = 4; off; off >>= 1) m = fmaxf(m, __shfl_down_sync(0xffu, m, off));
        if (threadIdx.x == 0) bcast = m;
    }
    __syncthreads();
    m = bcast;

    float s = 0.f;
    for (int p = threadIdx.x; p < HW; p += 256) s += expf(kp[p] - m);
    __syncthreads();
#pragma unroll
    for (int off = 16; off; off >>= 1) s += __shfl_down_sync(0xffffffffu, s, off);
    if ((threadIdx.x & 31) == 0) red[threadIdx.x >> 5] = s;
    __syncthreads();
    if (threadIdx.x < 8) {
        s = red[threadIdx.x];
#pragma unroll
        for (int off = 4; off; off >>= 1) s += __shfl_down_sync(0xffu, s, off);
        if (threadIdx.x == 0) {
            g_kmax[row] = m;
            g_ksum[row] = s;
        }
    }
}

// ---------------- content_lambda[bh][i][o] = sum_n softmax(k)[i][n] * v[o][n] ----------------
__global__ void k_lambda() {
    int bh = blockIdx.x;
    int b = bh >> 3, nh = bh & 7;
    const float* kbase = g_qkv + ((size_t)b * OC3 + CC + nh * HDIM) * HW;
    const float* vbase = g_qkv + ((size_t)b * OC3 + 2 * CC + nh * HDIM) * HW;
    __shared__ float ks[HDIM][129];
    __shared__ float vs[HDIM][129];
    __shared__ float kmax_s[HDIM];
    int tid = threadIdx.x;
    int i = tid >> 4, o = tid & 15;
    if (tid < HDIM) kmax_s[tid] = g_kmax[bh * HDIM + tid];
    __syncthreads();
    float acc = 0.f;
    for (int c0 = 0; c0 < HW; c0 += 128) {
        for (int t = tid; t < HDIM * 128; t += 256) {
            int r = t >> 7, j = t & 127;
            ks[r][j] = kbase[(size_t)r * HW + c0 + j];
            vs[r][j] = vbase[(size_t)r * HW + c0 + j];
        }
        __syncthreads();
        for (int t = tid; t < HDIM * 128; t += 256) {
            int r = t >> 7, j = t & 127;
            ks[r][j] = expf(ks[r][j] - kmax_s[r]);
        }
        __syncthreads();
#pragma unroll 8
        for (int j = 0; j < 128; j++) acc += ks[i][j] * vs[o][j];
        __syncthreads();
    }
    float inv = 1.f / g_ksum[bh * HDIM + i];
    g_lam[(bh * HDIM + i) * HDIM + o] = acc * inv;
}

// ---------------- position lambda: depthwise 5x5 of v ----------------
__global__ void k_pos(const float* __restrict__ rel) {
    int bc = blockIdx.x;
    int b = bc >> 7, c = bc & 127;
    const float* vp = g_qkv + ((size_t)b * OC3 + 2 * CC + c) * HW;
    const float* w = rel + (c & 15) * 25;
    __shared__ float t[68][68];
    for (int i = threadIdx.x; i < 68 * 68; i += blockDim.x) {
        int r = i / 68, q = i % 68;
        int rr = r - 2, qq = q - 2;
        t[r][q] = (rr >= 0 && rr < 64 && qq >= 0 && qq < 64) ? vp[rr * 64 + qq] : 0.f;
    }
    __syncthreads();
    float wr[25];
#pragma unroll
    for (int j = 0; j < 25; j++) wr[j] = w[j];
    for (int p = threadIdx.x; p < HW; p += blockDim.x) {
        int r = p >> 6, q = p & 63;
        float acc = 0.f;
#pragma unroll
        for (int dr = 0; dr < 5; dr++)
#pragma unroll
            for (int dc = 0; dc < 5; dc++)
                acc += wr[dr * 5 + dc] * t[r + dr][q + dc];
        g_poslam[(size_t)bc * HW + p] = acc;
    }
}

// ---------------- combine: res1 = 0.25 * (q^T lam) + q * poslam ----------------
__global__ void k_combine() {
    int bh = blockIdx.y;
    int b = bh >> 3, nh = bh & 7;
    int n = blockIdx.x * 256 + threadIdx.x;
    __shared__ float lam[HDIM][HDIM + 1];
    lam[threadIdx.x >> 4][threadIdx.x & 15] = g_lam[bh * 256 + threadIdx.x];
    __syncthreads();
    const float* qbase = g_qkv + ((size_t)b * OC3 + nh * HDIM) * HW;
    const float* plbase = g_poslam + (size_t)(b * CC + nh * HDIM) * HW;
    float* rbase = g_res1 + (size_t)(b * CC + nh * HDIM) * HW;
    float qv[16];
#pragma unroll
    for (int i = 0; i < 16; i++) qv[i] = qbase[(size_t)i * HW + n];
    const float scaling = 0.25f;  // HD^-0.5
#pragma unroll
    for (int o = 0; o < 16; o++) {
        float cacc = 0.f;
#pragma unroll
        for (int i = 0; i < 16; i++) cacc += qv[i] * lam[i][o];
        rbase[(size_t)o * HW + n] = cacc * scaling + qv[o] * plbase[(size_t)o * HW + n];
    }
}

// ---------------- final GEMM with fused concat + channel attention ----------------
// out[b][o][n] = sum_{k<128} W[o][k]*res1[b][k][n] + sum_{k>=128} W[o][k]*src[b][k-128][n]*ca[b][k-128]
__global__ void k_gemm_final(const float* __restrict__ Wm, const float* __restrict__ src,
                             float* __restrict__ Out) {
    const int BM = 64, BN = 64, BK = 32, KC = 256;
    __shared__ float Ws[BK][BM + 1];
    __shared__ float Is[BK][BN + 4];
    int b = blockIdx.z;
    int o0 = blockIdx.y * BM;
    int n0 = blockIdx.x * BN;
    int tid = threadIdx.x, tx = tid & 15, ty = tid >> 4;
    float acc[4][4] = {};
    for (int k0 = 0; k0 < KC; k0 += BK) {
        for (int i = tid; i < BM * BK; i += 256) {
            int o = i >> 5, k = i & 31;
            Ws[k][o] = Wm[(o0 + o) * KC + k0 + k];
        }
        for (int i = tid; i < BK * BN; i += 256) {
            int k = i >> 6, n = i & 63;
            int kg = k0 + k;
            float v;
            if (kg < CC) {
                v = g_res1[((size_t)b * CC + kg) * HW + n0 + n];
            } else {
                int c = kg - CC;
                v = src[((size_t)b * CC + c) * HW + n0 + n] * g_ca[b * CC + c];
            }
            Is[k][n] = v;
        }
        __syncthreads();
#pragma unroll
        for (int kk = 0; kk < BK; kk++) {
            float a[4], bv[4];
#pragma unroll
            for (int i = 0; i < 4; i++) a[i] = Ws[kk][ty * 4 + i];
#pragma unroll
            for (int j = 0; j < 4; j++) bv[j] = Is[kk][tx * 4 + j];
#pragma unroll
            for (int i = 0; i < 4; i++)
#pragma unroll
                for (int j = 0; j < 4; j++)
                    acc[i][j] += a[i] * bv[j];
        }
        __syncthreads();
    }
    float* Ob = Out + (size_t)b * OUTC * HW;
#pragma unroll
    for (int i = 0; i < 4; i++)
#pragma unroll
        for (int j = 0; j < 4; j++)
            Ob[(size_t)(o0 + ty * 4 + i) * HW + n0 + tx * 4 + j] = acc[i][j];
}

extern "C" void kernel_launch(void* const* d_in, const int* in_sizes, int n_in,
                              void* d_out, int out_size) {
    const float* src    = (const float*)d_in[0];  // (16,128,64,64)
    const float* cpe_w  = (const float*)d_in[1];  // (128,1,3,3)
    const float* qkv_w  = (const float*)d_in[2];  // (384,128)
    const float* rel    = (const float*)d_in[3];  // (16,5,5)
    const float* c1d    = (const float*)d_in[4];  // (3,)
    const float* out_w  = (const float*)d_in[5];  // (512,256)
    float* out = (float*)d_out;                   // (16,512,64,64)

    k_cpe<<<BB * CC, 256>>>(src, cpe_w);
    k_pool<<<BB * CC, 256>>>(src);
    k_ca<<<BB, CC>>>(c1d);
    k_gemm_qkv<<<dim3(HW / 64, OC3 / 64, BB), 256>>>(qkv_w);
    k_kstats<<<BH * HDIM, 256>>>();
    k_lambda<<<BH, 256>>>();
    k_pos<<<BB * CC, 256>>>(rel);
    k_combine<<<dim3(HW / 256, BH), 256>>>();
    k_gemm_final<<<dim3(HW / 64, OUTC / 64, BB), 256>>>(out_w, src, out);
}

// round 4
// speedup vs baseline: 1.4906x; 1.4906x over previous
#include <cuda_runtime.h>
#include <math.h>

#define BB 16
#define CC 128
#define HW 4096
#define NHEAD 8
#define HDIM 16
#define BH 128
#define OC3 384
#define OUTC 512

// Scratch (allocation-free rule: __device__ globals)
__device__ float g_s[(size_t)BB * CC * HW];        // CPE output
__device__ float g_qkv[(size_t)BB * OC3 * HW];     // qkv per batch [384][4096]
__device__ float g_poslam[(size_t)BB * CC * HW];   // position lambda
__device__ float g_res1[(size_t)BB * CC * HW];     // result1
__device__ float g_pool[BB * CC];
__device__ float g_ca[BB * CC];
__device__ float g_kmax[BH * HDIM];
__device__ float g_ksum[BH * HDIM];
__device__ float g_lam[BH * HDIM * HDIM];

// ---------------- CPE: depthwise 3x3 + residual, fused global-mean pool ----------------
__global__ void k_cpe(const float* __restrict__ src, const float* __restrict__ cpe_w) {
    int bc = blockIdx.x;              // b*C + c
    int c = bc & (CC - 1);
    const float* plane = src + (size_t)bc * HW;
    __shared__ float t[66][66];
    __shared__ float red[8];
    for (int i = threadIdx.x; i < 66 * 66; i += blockDim.x) {
        int r = i / 66, q = i % 66;
        int rr = r - 1, qq = q - 1;
        t[r][q] = (rr >= 0 && rr < 64 && qq >= 0 && qq < 64) ? plane[rr * 64 + qq] : 0.f;
    }
    __syncthreads();
    float w[9];
#pragma unroll
    for (int j = 0; j < 9; j++) w[j] = cpe_w[c * 9 + j];
    float psum = 0.f;
    for (int p = threadIdx.x; p < HW; p += blockDim.x) {
        int r = p >> 6, q = p & 63;
        float center = t[r + 1][q + 1];
        psum += center;
        float acc = center;  // residual
#pragma unroll
        for (int dr = 0; dr < 3; dr++)
#pragma unroll
            for (int dc = 0; dc < 3; dc++)
                acc += w[dr * 3 + dc] * t[r + dr][q + dc];
        g_s[(size_t)bc * HW + p] = acc;
    }
    // block reduce psum -> pooled mean
#pragma unroll
    for (int off = 16; off; off >>= 1) psum += __shfl_down_sync(0xffffffffu, psum, off);
    if ((threadIdx.x & 31) == 0) red[threadIdx.x >> 5] = psum;
    __syncthreads();
    if (threadIdx.x < 8) {
        psum = red[threadIdx.x];
#pragma unroll
        for (int off = 4; off; off >>= 1) psum += __shfl_down_sync(0xffu, psum, off);
        if (threadIdx.x == 0) g_pool[bc] = psum * (1.f / HW);
    }
}

// ---------------- ECA conv1d + sigmoid ----------------
__global__ void k_ca(const float* __restrict__ w3) {
    int b = blockIdx.x, c = threadIdx.x;
    const float* pp = g_pool + b * CC;
    float x0 = (c > 0) ? pp[c - 1] : 0.f;
    float x1 = pp[c];
    float x2 = (c < CC - 1) ? pp[c + 1] : 0.f;
    float z = w3[0] * x0 + w3[1] * x1 + w3[2] * x2;
    g_ca[b * CC + c] = 1.f / (1.f + expf(-z));
}

// ================= 128x128x32 GEMM, 256 threads, 8x8 micro-tile =================
// D[b][o0+..][n0+..] = sum_k W[o][k] * In[b][k][n]
// Micro-tile rows: ty*4+i and ty*4+64+i ; cols: tx*4+j and tx*4+64+j

__global__ void __launch_bounds__(256) k_gemm_qkv(const float* __restrict__ Wm) {
    const int BK = 32, KC = 128;
    __shared__ float As[BK][128];
    __shared__ float Is[BK][128];
    int b = blockIdx.z;
    int o0 = blockIdx.y * 128;
    int n0 = blockIdx.x * 128;
    const float* Inb = g_s + (size_t)b * KC * HW;
    int tid = threadIdx.x, tx = tid & 15, ty = tid >> 4;
    // A-loader indices: each thread covers one m row half of K-chunk
    int am = tid >> 1, ah = (tid & 1) * 16;
    // B-loader indices: row k = tid>>3, 8 threads per row
    int bk = tid >> 3, bn = (tid & 7) * 4;

    float acc[8][8] = {};
    for (int k0 = 0; k0 < KC; k0 += BK) {
        // load A^T tile: As[k][m]
        const float* wrow = Wm + (size_t)(o0 + am) * KC + k0 + ah;
#pragma unroll
        for (int q = 0; q < 4; q++) {
            float4 w4 = *(const float4*)(wrow + q * 4);
            As[ah + q * 4 + 0][am] = w4.x;
            As[ah + q * 4 + 1][am] = w4.y;
            As[ah + q * 4 + 2][am] = w4.z;
            As[ah + q * 4 + 3][am] = w4.w;
        }
        // load input tile: Is[k][n]
        const float* irow = Inb + (size_t)(k0 + bk) * HW + n0;
#pragma unroll
        for (int u = 0; u < 4; u++) {
            *(float4*)&Is[bk][bn + u * 32] = *(const float4*)(irow + bn + u * 32);
        }
        __syncthreads();
#pragma unroll
        for (int kk = 0; kk < BK; kk++) {
            float4 a0 = *(const float4*)&As[kk][ty * 4];
            float4 a1 = *(const float4*)&As[kk][ty * 4 + 64];
            float4 b0 = *(const float4*)&Is[kk][tx * 4];
            float4 b1 = *(const float4*)&Is[kk][tx * 4 + 64];
            float ar[8] = {a0.x, a0.y, a0.z, a0.w, a1.x, a1.y, a1.z, a1.w};
            float br[8] = {b0.x, b0.y, b0.z, b0.w, b1.x, b1.y, b1.z, b1.w};
#pragma unroll
            for (int i = 0; i < 8; i++)
#pragma unroll
                for (int j = 0; j < 8; j++)
                    acc[i][j] += ar[i] * br[j];
        }
        __syncthreads();
    }
    float* Ob = g_qkv + (size_t)b * OC3 * HW;
#pragma unroll
    for (int i = 0; i < 8; i++) {
        int row = o0 + ((i < 4) ? (ty * 4 + i) : (ty * 4 + 64 + i - 4));
        float4 v0 = make_float4(acc[i][0], acc[i][1], acc[i][2], acc[i][3]);
        float4 v1 = make_float4(acc[i][4], acc[i][5], acc[i][6], acc[i][7]);
        *(float4*)(Ob + (size_t)row * HW + n0 + tx * 4) = v0;
        *(float4*)(Ob + (size_t)row * HW + n0 + tx * 4 + 64) = v1;
    }
}

// ---------------- softmax stats over spatial dim of k ----------------
__global__ void k_kstats() {
    int row = blockIdx.x;            // bh*16 + i
    int bh = row >> 4, i = row & 15;
    int b = bh >> 3, nh = bh & 7;
    const float* kp = g_qkv + ((size_t)b * OC3 + CC + nh * HDIM + i) * HW;
    __shared__ float red[8];
    __shared__ float bcast;

    float m = -1e30f;
    for (int p = threadIdx.x; p < HW; p += 256) m = fmaxf(m, kp[p]);
#pragma unroll
    for (int off = 16; off; off >>= 1) m = fmaxf(m, __shfl_down_sync(0xffffffffu, m, off));
    if ((threadIdx.x & 31) == 0) red[threadIdx.x >> 5] = m;
    __syncthreads();
    if (threadIdx.x < 8) {
        m = red[threadIdx.x];
#pragma unroll
        for (int off = 4; off; off >>= 1) m = fmaxf(m, __shfl_down_sync(0xffu, m, off));
        if (threadIdx.x == 0) bcast = m;
    }
    __syncthreads();
    m = bcast;

    float s = 0.f;
    for (int p = threadIdx.x; p < HW; p += 256) s += expf(kp[p] - m);
    __syncthreads();
#pragma unroll
    for (int off = 16; off; off >>= 1) s += __shfl_down_sync(0xffffffffu, s, off);
    if ((threadIdx.x & 31) == 0) red[threadIdx.x >> 5] = s;
    __syncthreads();
    if (threadIdx.x < 8) {
        s = red[threadIdx.x];
#pragma unroll
        for (int off = 4; off; off >>= 1) s += __shfl_down_sync(0xffu, s, off);
        if (threadIdx.x == 0) {
            g_kmax[row] = m;
            g_ksum[row] = s;
        }
    }
}

// ---------------- content_lambda[bh][i][o] = sum_n softmax(k)[i][n] * v[o][n] ----------------
__global__ void k_lambda() {
    int bh = blockIdx.x;
    int b = bh >> 3, nh = bh & 7;
    const float* kbase = g_qkv + ((size_t)b * OC3 + CC + nh * HDIM) * HW;
    const float* vbase = g_qkv + ((size_t)b * OC3 + 2 * CC + nh * HDIM) * HW;
    __shared__ float ks[HDIM][129];
    __shared__ float vs[HDIM][129];
    __shared__ float kmax_s[HDIM];
    int tid = threadIdx.x;
    int i = tid >> 4, o = tid & 15;
    if (tid < HDIM) kmax_s[tid] = g_kmax[bh * HDIM + tid];
    __syncthreads();
    float acc = 0.f;
    for (int c0 = 0; c0 < HW; c0 += 128) {
        for (int t = tid; t < HDIM * 128; t += 256) {
            int r = t >> 7, j = t & 127;
            ks[r][j] = kbase[(size_t)r * HW + c0 + j];
            vs[r][j] = vbase[(size_t)r * HW + c0 + j];
        }
        __syncthreads();
        for (int t = tid; t < HDIM * 128; t += 256) {
            int r = t >> 7, j = t & 127;
            ks[r][j] = expf(ks[r][j] - kmax_s[r]);
        }
        __syncthreads();
#pragma unroll 8
        for (int j = 0; j < 128; j++) acc += ks[i][j] * vs[o][j];
        __syncthreads();
    }
    float inv = 1.f / g_ksum[bh * HDIM + i];
    g_lam[(bh * HDIM + i) * HDIM + o] = acc * inv;
}

// ---------------- position lambda: depthwise 5x5 of v ----------------
__global__ void k_pos(const float* __restrict__ rel) {
    int bc = blockIdx.x;
    int b = bc >> 7, c = bc & 127;
    const float* vp = g_qkv + ((size_t)b * OC3 + 2 * CC + c) * HW;
    const float* w = rel + (c & 15) * 25;
    __shared__ float t[68][68];
    for (int i = threadIdx.x; i < 68 * 68; i += blockDim.x) {
        int r = i / 68, q = i % 68;
        int rr = r - 2, qq = q - 2;
        t[r][q] = (rr >= 0 && rr < 64 && qq >= 0 && qq < 64) ? vp[rr * 64 + qq] : 0.f;
    }
    __syncthreads();
    float wr[25];
#pragma unroll
    for (int j = 0; j < 25; j++) wr[j] = w[j];
    for (int p = threadIdx.x; p < HW; p += blockDim.x) {
        int r = p >> 6, q = p & 63;
        float acc = 0.f;
#pragma unroll
        for (int dr = 0; dr < 5; dr++)
#pragma unroll
            for (int dc = 0; dc < 5; dc++)
                acc += wr[dr * 5 + dc] * t[r + dr][q + dc];
        g_poslam[(size_t)bc * HW + p] = acc;
    }
}

// ---------------- combine: res1 = 0.25 * (q^T lam) + q * poslam ----------------
__global__ void k_combine() {
    int bh = blockIdx.y;
    int b = bh >> 3, nh = bh & 7;
    int n = blockIdx.x * 256 + threadIdx.x;
    __shared__ float lam[HDIM][HDIM + 1];
    lam[threadIdx.x >> 4][threadIdx.x & 15] = g_lam[bh * 256 + threadIdx.x];
    __syncthreads();
    const float* qbase = g_qkv + ((size_t)b * OC3 + nh * HDIM) * HW;
    const float* plbase = g_poslam + (size_t)(b * CC + nh * HDIM) * HW;
    float* rbase = g_res1 + (size_t)(b * CC + nh * HDIM) * HW;
    float qv[16];
#pragma unroll
    for (int i = 0; i < 16; i++) qv[i] = qbase[(size_t)i * HW + n];
    const float scaling = 0.25f;  // HD^-0.5
#pragma unroll
    for (int o = 0; o < 16; o++) {
        float cacc = 0.f;
#pragma unroll
        for (int i = 0; i < 16; i++) cacc += qv[i] * lam[i][o];
        rbase[(size_t)o * HW + n] = cacc * scaling + qv[o] * plbase[(size_t)o * HW + n];
    }
}

// ---------------- final GEMM (128x128x32, 8x8 micro) with fused concat + channel attention --
__global__ void __launch_bounds__(256) k_gemm_final(const float* __restrict__ Wm,
                                                    const float* __restrict__ src,
                                                    float* __restrict__ Out) {
    const int BK = 32, KC = 256;
    __shared__ float As[BK][128];
    __shared__ float Is[BK][128];
    int b = blockIdx.z;
    int o0 = blockIdx.y * 128;
    int n0 = blockIdx.x * 128;
    int tid = threadIdx.x, tx = tid & 15, ty = tid >> 4;
    int am = tid >> 1, ah = (tid & 1) * 16;
    int bk = tid >> 3, bn = (tid & 7) * 4;

    float acc[8][8] = {};
    for (int k0 = 0; k0 < KC; k0 += BK) {
        const float* wrow = Wm + (size_t)(o0 + am) * KC + k0 + ah;
#pragma unroll
        for (int q = 0; q < 4; q++) {
            float4 w4 = *(const float4*)(wrow + q * 4);
            As[ah + q * 4 + 0][am] = w4.x;
            As[ah + q * 4 + 1][am] = w4.y;
            As[ah + q * 4 + 2][am] = w4.z;
            As[ah + q * 4 + 3][am] = w4.w;
        }
        // input tile: k<128 -> res1, k>=128 -> src * ca
        int kg = k0 + bk;
        const float* irow;
        float scale;
        if (kg < CC) {
            irow = g_res1 + ((size_t)b * CC + kg) * HW + n0;
            scale = 1.f;
        } else {
            int c = kg - CC;
            irow = src + ((size_t)b * CC + c) * HW + n0;
            scale = g_ca[b * CC + c];
        }
#pragma unroll
        for (int u = 0; u < 4; u++) {
            float4 v = *(const float4*)(irow + bn + u * 32);
            v.x *= scale; v.y *= scale; v.z *= scale; v.w *= scale;
            *(float4*)&Is[bk][bn + u * 32] = v;
        }
        __syncthreads();
#pragma unroll
        for (int kk = 0; kk < BK; kk++) {
            float4 a0 = *(const float4*)&As[kk][ty * 4];
            float4 a1 = *(const float4*)&As[kk][ty * 4 + 64];
            float4 b0 = *(const float4*)&Is[kk][tx * 4];
            float4 b1 = *(const float4*)&Is[kk][tx * 4 + 64];
            float ar[8] = {a0.x, a0.y, a0.z, a0.w, a1.x, a1.y, a1.z, a1.w};
            float br[8] = {b0.x, b0.y, b0.z, b0.w, b1.x, b1.y, b1.z, b1.w};
#pragma unroll
            for (int i = 0; i < 8; i++)
#pragma unroll
                for (int j = 0; j < 8; j++)
                    acc[i][j] += ar[i] * br[j];
        }
        __syncthreads();
    }
    float* Ob = Out + (size_t)b * OUTC * HW;
#pragma unroll
    for (int i = 0; i < 8; i++) {
        int row = o0 + ((i < 4) ? (ty * 4 + i) : (ty * 4 + 64 + i - 4));
        float4 v0 = make_float4(acc[i][0], acc[i][1], acc[i][2], acc[i][3]);
        float4 v1 = make_float4(acc[i][4], acc[i][5], acc[i][6], acc[i][7]);
        *(float4*)(Ob + (size_t)row * HW + n0 + tx * 4) = v0;
        *(float4*)(Ob + (size_t)row * HW + n0 + tx * 4 + 64) = v1;
    }
}

extern "C" void kernel_launch(void* const* d_in, const int* in_sizes, int n_in,
                              void* d_out, int out_size) {
    const float* src    = (const float*)d_in[0];  // (16,128,64,64)
    const float* cpe_w  = (const float*)d_in[1];  // (128,1,3,3)
    const float* qkv_w  = (const float*)d_in[2];  // (384,128)
    const float* rel    = (const float*)d_in[3];  // (16,5,5)
    const float* c1d    = (const float*)d_in[4];  // (3,)
    const float* out_w  = (const float*)d_in[5];  // (512,256)
    float* out = (float*)d_out;                   // (16,512,64,64)

    k_cpe<<<BB * CC, 256>>>(src, cpe_w);
    k_ca<<<BB, CC>>>(c1d);
    k_gemm_qkv<<<dim3(HW / 128, OC3 / 128, BB), 256>>>(qkv_w);
    k_kstats<<<BH * HDIM, 256>>>();
    k_lambda<<<BH, 256>>>();
    k_pos<<<BB * CC, 256>>>(rel);
    k_combine<<<dim3(HW / 256, BH), 256>>>();
    k_gemm_final<<<dim3(HW / 128, OUTC / 128, BB), 256>>>(out_w, src, out);
}

// round 7
// speedup vs baseline: 1.5468x; 1.0377x over previous
#include <cuda_runtime.h>
#include <math.h>
#include <stdint.h>

#define BB 16
#define CC 128
#define HW 4096
#define NHEAD 8
#define HDIM 16
#define BH 128
#define OC3 384
#define OUTC 512

// Scratch (allocation-free rule: __device__ globals)
__device__ float g_s[(size_t)BB * CC * HW];        // CPE output
__device__ float g_qkv[(size_t)BB * OC3 * HW];     // qkv per batch [384][4096]
__device__ float g_poslam[(size_t)BB * CC * HW];   // position lambda
__device__ float g_cat[(size_t)BB * 2 * CC * HW];  // [res1 | src*ca] per batch [256][4096]
__device__ float g_pool[BB * CC];
__device__ float g_ca[BB * CC];
__device__ float g_lam[BH * HDIM * HDIM];

__device__ __forceinline__ uint32_t smem_u32(const void* p) {
    uint32_t a;
    asm("{ .reg .u64 tmp; cvta.to.shared.u64 tmp, %1; cvt.u32.u64 %0, tmp; }"
        : "=r"(a) : "l"(p));
    return a;
}
__device__ __forceinline__ void cp_async16(uint32_t dst, const void* src) {
    asm volatile("cp.async.cg.shared.global [%0], [%1], 16;" :: "r"(dst), "l"(src) : "memory");
}

// ================= double-buffered 128x128x32 GEMM, 256 threads, 8x8 micro-tile ======
// Out[b][o][n] = sum_k W[o][k] * Bmat[b][k][n]
// dynamic smem: As[2][32][128] @0, Is[2][32][128] @32768  (64 KB total)
#define AS_OFF 0
#define IS_OFF 32768
#define GEMM_SMEM 65536

__global__ void __launch_bounds__(256, 2) k_gemm(const float* __restrict__ Wm,
                                                 const float* __restrict__ Bbase,
                                                 float* __restrict__ Obase,
                                                 int KC, int orpb) {
    extern __shared__ char sm[];
    float* As = (float*)(sm + AS_OFF);       // [2][32][128]
    float* Is = (float*)(sm + IS_OFF);       // [2][32][128]
    uint32_t is_u32 = smem_u32(Is);

    int b = blockIdx.z;
    int o0 = blockIdx.y * 128;
    int n0 = blockIdx.x * 128;
    int tid = threadIdx.x, tx = tid & 15, ty = tid >> 4;
    int am = tid >> 1, ah = (tid & 1) * 16;  // A: 2 threads/row, 16 k each
    int bk = tid >> 3, bn = (tid & 7) * 4;   // B: 8 threads/row, 4x float4 each

    const float* Bb = Bbase + (size_t)b * KC * HW;
    const float* wrowbase = Wm + (size_t)(o0 + am) * KC + ah;

    int nchunk = KC >> 5;

    float4 areg[4];
    // prologue: A(0) regs + B(0) cp.async into buf0
#pragma unroll
    for (int q = 0; q < 4; q++)
        areg[q] = *(const float4*)(wrowbase + q * 4);
#pragma unroll
    for (int u = 0; u < 4; u++)
        cp_async16(is_u32 + (uint32_t)(bk * 512 + (bn + u * 32) * 4),
                   Bb + (size_t)bk * HW + n0 + bn + u * 32);
    asm volatile("cp.async.commit_group;" ::: "memory");
    // store A(0) into As buf0 (visible after first sync)
    {
        float* a0 = As;
#pragma unroll
        for (int q = 0; q < 4; q++) {
            a0[(ah + q * 4 + 0) * 128 + am] = areg[q].x;
            a0[(ah + q * 4 + 1) * 128 + am] = areg[q].y;
            a0[(ah + q * 4 + 2) * 128 + am] = areg[q].z;
            a0[(ah + q * 4 + 3) * 128 + am] = areg[q].w;
        }
    }

    float acc[8][8] = {};
    int buf = 0;
    for (int ch = 0; ch < nchunk; ch++) {
        int has_next = (ch + 1 < nchunk);
        if (has_next) {
            int k0n = (ch + 1) << 5;
            // issue B(ch+1) into other buffer
            uint32_t dstb = is_u32 + (uint32_t)((buf ^ 1) * 16384);
            const float* srow = Bb + (size_t)(k0n + bk) * HW + n0;
#pragma unroll
            for (int u = 0; u < 4; u++)
                cp_async16(dstb + (uint32_t)(bk * 512 + (bn + u * 32) * 4),
                           srow + bn + u * 32);
            asm volatile("cp.async.commit_group;" ::: "memory");
            // A(ch+1) global -> regs
#pragma unroll
            for (int q = 0; q < 4; q++)
                areg[q] = *(const float4*)(wrowbase + k0n + q * 4);
            asm volatile("cp.async.wait_group 1;" ::: "memory");
        } else {
            asm volatile("cp.async.wait_group 0;" ::: "memory");
        }
        __syncthreads();
        if (has_next) {
            // store A(ch+1) into other buffer (no reader conflicts)
            float* a1 = As + (buf ^ 1) * (32 * 128);
#pragma unroll
            for (int q = 0; q < 4; q++) {
                a1[(ah + q * 4 + 0) * 128 + am] = areg[q].x;
                a1[(ah + q * 4 + 1) * 128 + am] = areg[q].y;
                a1[(ah + q * 4 + 2) * 128 + am] = areg[q].z;
                a1[(ah + q * 4 + 3) * 128 + am] = areg[q].w;
            }
        }
        const float* Ab = As + buf * (32 * 128);
        const float* Ib = Is + buf * (32 * 128);
#pragma unroll
        for (int kk = 0; kk < 32; kk++) {
            float4 a0 = *(const float4*)(Ab + kk * 128 + ty * 4);
            float4 a1 = *(const float4*)(Ab + kk * 128 + ty * 4 + 64);
            float4 b0 = *(const float4*)(Ib + kk * 128 + tx * 4);
            float4 b1 = *(const float4*)(Ib + kk * 128 + tx * 4 + 64);
            float ar[8] = {a0.x, a0.y, a0.z, a0.w, a1.x, a1.y, a1.z, a1.w};
            float br[8] = {b0.x, b0.y, b0.z, b0.w, b1.x, b1.y, b1.z, b1.w};
#pragma unroll
            for (int i = 0; i < 8; i++)
#pragma unroll
                for (int j = 0; j < 8; j++)
                    acc[i][j] += ar[i] * br[j];
        }
        __syncthreads();
        buf ^= 1;
    }
    float* Ob = Obase + (size_t)b * orpb * HW;
#pragma unroll
    for (int i = 0; i < 8; i++) {
        int row = o0 + ((i < 4) ? (ty * 4 + i) : (ty * 4 + 64 + i - 4));
        float4 v0 = make_float4(acc[i][0], acc[i][1], acc[i][2], acc[i][3]);
        float4 v1 = make_float4(acc[i][4], acc[i][5], acc[i][6], acc[i][7]);
        *(float4*)(Ob + (size_t)row * HW + n0 + tx * 4) = v0;
        *(float4*)(Ob + (size_t)row * HW + n0 + tx * 4 + 64) = v1;
    }
}

// ---------------- CPE: depthwise 3x3 + residual, fused global-mean pool ----------------
__global__ void k_cpe(const float* __restrict__ src, const float* __restrict__ cpe_w) {
    int bc = blockIdx.x;              // b*C + c
    int c = bc & (CC - 1);
    const float* plane = src + (size_t)bc * HW;
    __shared__ float t[66][66];
    __shared__ float red[8];
    for (int i = threadIdx.x; i < 66 * 66; i += blockDim.x) {
        int r = i / 66, q = i % 66;
        int rr = r - 1, qq = q - 1;
        t[r][q] = (rr >= 0 && rr < 64 && qq >= 0 && qq < 64) ? plane[rr * 64 + qq] : 0.f;
    }
    __syncthreads();
    float w[9];
#pragma unroll
    for (int j = 0; j < 9; j++) w[j] = cpe_w[c * 9 + j];
    float psum = 0.f;
    for (int p = threadIdx.x; p < HW; p += blockDim.x) {
        int r = p >> 6, q = p & 63;
        float center = t[r + 1][q + 1];
        psum += center;
        float acc = center;  // residual
#pragma unroll
        for (int dr = 0; dr < 3; dr++)
#pragma unroll
            for (int dc = 0; dc < 3; dc++)
                acc += w[dr * 3 + dc] * t[r + dr][q + dc];
        g_s[(size_t)bc * HW + p] = acc;
    }
#pragma unroll
    for (int off = 16; off; off >>= 1) psum += __shfl_down_sync(0xffffffffu, psum, off);
    if ((threadIdx.x & 31) == 0) red[threadIdx.x >> 5] = psum;
    __syncthreads();
    if (threadIdx.x < 8) {
        psum = red[threadIdx.x];
#pragma unroll
        for (int off = 4; off; off >>= 1) psum += __shfl_down_sync(0xffu, psum, off);
        if (threadIdx.x == 0) g_pool[bc] = psum * (1.f / HW);
    }
}

// ---------------- ECA conv1d + sigmoid ----------------
__global__ void k_ca(const float* __restrict__ w3) {
    int b = blockIdx.x, c = threadIdx.x;
    const float* pp = g_pool + b * CC;
    float x0 = (c > 0) ? pp[c - 1] : 0.f;
    float x1 = pp[c];
    float x2 = (c < CC - 1) ? pp[c + 1] : 0.f;
    float z = w3[0] * x0 + w3[1] * x1 + w3[2] * x2;
    g_ca[b * CC + c] = 1.f / (1.f + expf(-z));
}

// ---------------- scale second half of cat: g_cat[b][128+c][:] = src * ca ----------------
__global__ void k_scale(const float* __restrict__ src) {
    int bc = blockIdx.x;
    int b = bc >> 7, c = bc & 127;
    float ca = g_ca[bc];
    const float* ip = src + (size_t)bc * HW;
    float* op = g_cat + ((size_t)b * 2 * CC + CC + c) * HW;
    for (int p = threadIdx.x * 4; p < HW; p += 256 * 4) {
        float4 v = *(const float4*)(ip + p);
        v.x *= ca; v.y *= ca; v.z *= ca; v.w *= ca;
        *(float4*)(op + p) = v;
    }
}

// ---------- content_lambda via ONLINE softmax: lam[bh][i][o] = sum_n sm(k)[i][n] v[o][n] ----
__global__ void k_lambda() {
    int bh = blockIdx.x;
    int b = bh >> 3, nh = bh & 7;
    const float* kbase = g_qkv + ((size_t)b * OC3 + CC + nh * HDIM) * HW;
    const float* vbase = g_qkv + ((size_t)b * OC3 + 2 * CC + nh * HDIM) * HW;
    __shared__ float ks[HDIM][129];
    __shared__ float vs[HDIM][129];
    int tid = threadIdx.x;
    int i = tid >> 4, o = tid & 15;
    float m = -1e30f, d = 0.f, acc = 0.f;
    for (int c0 = 0; c0 < HW; c0 += 128) {
        for (int t = tid; t < HDIM * 128; t += 256) {
            int r = t >> 7, j = t & 127;
            ks[r][j] = kbase[(size_t)r * HW + c0 + j];
            vs[r][j] = vbase[(size_t)r * HW + c0 + j];
        }
        __syncthreads();
        // chunk max of row i (16 lanes of this row live in this warp)
        float mc = -1e30f;
#pragma unroll
        for (int t = 0; t < 8; t++) mc = fmaxf(mc, ks[i][o + t * 16]);
#pragma unroll
        for (int msk = 1; msk < 16; msk <<= 1)
            mc = fmaxf(mc, __shfl_xor_sync(0xffffffffu, mc, msk));
        float mnew = fmaxf(m, mc);
        float corr = expf(m - mnew);
        d *= corr; acc *= corr;
        // exp in place + chunk denom
        float ps = 0.f;
#pragma unroll
        for (int t = 0; t < 8; t++) {
            float e = expf(ks[i][o + t * 16] - mnew);
            ks[i][o + t * 16] = e;
            ps += e;
        }
#pragma unroll
        for (int msk = 1; msk < 16; msk <<= 1)
            ps += __shfl_xor_sync(0xffffffffu, ps, msk);
        d += ps;
        m = mnew;
        __syncwarp();   // row i's exp writes visible within the owning warp
#pragma unroll 8
        for (int j = 0; j < 128; j++) acc += ks[i][j] * vs[o][j];
        __syncthreads();
    }
    g_lam[(bh * HDIM + i) * HDIM + o] = acc / d;
}

// ---------------- position lambda: depthwise 5x5 of v ----------------
__global__ void k_pos(const float* __restrict__ rel) {
    int bc = blockIdx.x;
    int b = bc >> 7, c = bc & 127;
    const float* vp = g_qkv + ((size_t)b * OC3 + 2 * CC + c) * HW;
    const float* w = rel + (c & 15) * 25;
    __shared__ float t[68][68];
    for (int i = threadIdx.x; i < 68 * 68; i += blockDim.x) {
        int r = i / 68, q = i % 68;
        int rr = r - 2, qq = q - 2;
        t[r][q] = (rr >= 0 && rr < 64 && qq >= 0 && qq < 64) ? vp[rr * 64 + qq] : 0.f;
    }
    __syncthreads();
    float wr[25];
#pragma unroll
    for (int j = 0; j < 25; j++) wr[j] = w[j];
    for (int p = threadIdx.x; p < HW; p += blockDim.x) {
        int r = p >> 6, q = p & 63;
        float acc = 0.f;
#pragma unroll
        for (int dr = 0; dr < 5; dr++)
#pragma unroll
            for (int dc = 0; dc < 5; dc++)
                acc += wr[dr * 5 + dc] * t[r + dr][q + dc];
        g_poslam[(size_t)bc * HW + p] = acc;
    }
}

// ---------------- combine: cat[0:128] = 0.25 * (q^T lam) + q * poslam ----------------
__global__ void k_combine() {
    int bh = blockIdx.y;
    int b = bh >> 3, nh = bh & 7;
    int n = blockIdx.x * 256 + threadIdx.x;
    __shared__ float lam[HDIM][HDIM + 1];
    lam[threadIdx.x >> 4][threadIdx.x & 15] = g_lam[bh * 256 + threadIdx.x];
    __syncthreads();
    const float* qbase = g_qkv + ((size_t)b * OC3 + nh * HDIM) * HW;
    const float* plbase = g_poslam + (size_t)(b * CC + nh * HDIM) * HW;
    float* rbase = g_cat + ((size_t)b * 2 * CC + nh * HDIM) * HW;
    float qv[16];
#pragma unroll
    for (int i = 0; i < 16; i++) qv[i] = qbase[(size_t)i * HW + n];
    const float scaling = 0.25f;  // HD^-0.5
#pragma unroll
    for (int o = 0; o < 16; o++) {
        float cacc = 0.f;
#pragma unroll
        for (int i = 0; i < 16; i++) cacc += qv[i] * lam[i][o];
        rbase[(size_t)o * HW + n] = cacc * scaling + qv[o] * plbase[(size_t)o * HW + n];
    }
}

extern "C" void kernel_launch(void* const* d_in, const int* in_sizes, int n_in,
                              void* d_out, int out_size) {
    const float* src    = (const float*)d_in[0];  // (16,128,64,64)
    const float* cpe_w  = (const float*)d_in[1];  // (128,1,3,3)
    const float* qkv_w  = (const float*)d_in[2];  // (384,128)
    const float* rel    = (const float*)d_in[3];  // (16,5,5)
    const float* c1d    = (const float*)d_in[4];  // (3,)
    const float* out_w  = (const float*)d_in[5];  // (512,256)
    float* out = (float*)d_out;                   // (16,512,64,64)

    static int smem_set = 0;
    if (!smem_set) {
        cudaFuncSetAttribute(k_gemm, cudaFuncAttributeMaxDynamicSharedMemorySize, GEMM_SMEM);
        smem_set = 1;
    }

    float* d_s;    cudaGetSymbolAddress((void**)&d_s, g_s);
    float* d_qkv;  cudaGetSymbolAddress((void**)&d_qkv, g_qkv);
    float* d_cat;  cudaGetSymbolAddress((void**)&d_cat, g_cat);

    k_cpe<<<BB * CC, 256>>>(src, cpe_w);
    k_ca<<<BB, CC>>>(c1d);
    k_scale<<<BB * CC, 256>>>(src);
    // QKV GEMM: M=384, N=4096, K=128
    k_gemm<<<dim3(HW / 128, OC3 / 128, BB), 256, GEMM_SMEM>>>(qkv_w, d_s, d_qkv, CC, OC3);
    k_lambda<<<BH, 256>>>();
    k_pos<<<BB * CC, 256>>>(rel);
    k_combine<<<dim3(HW / 256, BH), 256>>>();
    // Final GEMM: M=512, N=4096, K=256 over g_cat
    k_gemm<<<dim3(HW / 128, OUTC / 128, BB), 256, GEMM_SMEM>>>(out_w, d_cat, out, 2 * CC, OUTC);
}